// round 6
// baseline (speedup 1.0000x reference)
#include <cuda_runtime.h>
#include <math.h>

// ---------------- problem constants ----------------
#define Dd   8
#define Ss   64
#define Hh   128
#define OUTD 8
#define Tt   2049
#define Bb   32
#define WINW 16
#define NWIN 128
#define Pp   28
#define NT   512

// padded smem strides (all ≡ 4 mod 32 -> conflict-free row access, 16B aligned)
#define W0S 68
#define W1S 132
#define VS  68
#define U0S 132
#define WTS 516
#define WRS 68

// smem float offsets (all multiples of 4)
#define OFF_WV0  0
#define OFF_WV1  (OFF_WV0 + 128*W0S)
#define OFF_U0T  (OFF_WV1 + 128*W1S)
#define OFF_WSMT (OFF_U0T + 8*U0S)
#define OFF_V    (OFF_WSMT + 8*WTS)
#define OFF_WR   (OFF_V   + 8*VS)
#define OFF_S1   (OFF_WR  + 8*WRS)
#define OFF_S2   (OFF_S1  + NWIN*Dd)
#define OFF_U1   (OFF_S2  + NWIN*Pp)
#define OFF_Z0   (OFF_U1  + 128*8)
#define OFF_D0   (OFF_Z0  + 128)
#define OFF_Z1   (OFF_D0  + 128)
#define OFF_D1   (OFF_Z1  + 128)
#define OFF_HA   (OFF_D1  + 128)
#define OFF_HB   (OFF_HA  + 64)
#define OFF_B0   (OFF_HB  + 64)
#define OFF_B1   (OFF_B0  + 128)
#define OFF_B2   (OFF_B1  + 128)
#define OFF_BR   (OFF_B2  + 512)
#define OFF_X0   (OFF_BR  + 8)
#define SMEM_FLOATS (OFF_X0 + 8)

// Wv2 (512x128) pre-transposed so stage C/F loads are coalesced:
// g_WT[(c*512 + r)*4 + j] = Wv2[r*128 + 4c + j]
__device__ float g_WT[512 * 128];

__global__ void wt_transpose_kernel(const float* __restrict__ Wv2) {
    int idx = blockIdx.x * blockDim.x + threadIdx.x;
    if (idx < 512 * 128) {
        int r = idx >> 7, k = idx & 127;
        int c = k >> 2, j = k & 3;
        g_WT[(c * 512 + r) * 4 + j] = Wv2[idx];
    }
}

__device__ __forceinline__ float softplusf(float x) {
    return fmaxf(x, 0.0f) + log1pf(expf(-fabsf(x)));
}
__device__ __forceinline__ float sigmf(float x) {
    return 1.0f / (1.0f + expf(-x));
}
__device__ __forceinline__ unsigned long long pack2(float lo, float hi) {
    unsigned long long r;
    asm("mov.b64 %0, {%1, %2};" : "=l"(r) : "f"(lo), "f"(hi));
    return r;
}
__device__ __forceinline__ unsigned long long fma2(unsigned long long a, unsigned long long b, unsigned long long c) {
    unsigned long long d;
    asm("fma.rn.f32x2 %0, %1, %2, %3;" : "=l"(d) : "l"(a), "l"(b), "l"(c));
    return d;
}
__device__ __forceinline__ float2 unpack2(unsigned long long v) {
    float2 f;
    asm("mov.b64 {%0, %1}, %2;" : "=f"(f.x), "=f"(f.y) : "l"(v));
    return f;
}

__global__ __launch_bounds__(NT, 1)
void logncde_kernel(const float* __restrict__ x,
                    const float* __restrict__ Wi0, const float* __restrict__ bi0,
                    const float* __restrict__ Wi1, const float* __restrict__ bi1,
                    const float* __restrict__ Wi2, const float* __restrict__ bi2,
                    const float* __restrict__ Wv0, const float* __restrict__ bv0,
                    const float* __restrict__ Wv1, const float* __restrict__ bv1,
                    const float* __restrict__ bv2,
                    const float* __restrict__ Wr,  const float* __restrict__ br,
                    float* __restrict__ out)
{
    extern __shared__ float sm[];
    const int t = threadIdx.x;
    const int b = blockIdx.x;

    // ---- load weights into padded smem ----
    for (int idx = t; idx < Hh * Ss; idx += NT) {
        int r = idx >> 6, a = idx & 63;
        sm[OFF_WV0 + r * W0S + a] = Wv0[idx];
    }
    for (int idx = t; idx < Hh * Hh; idx += NT) {
        int r = idx >> 7, k = idx & 127;
        sm[OFF_WV1 + r * W1S + k] = Wv1[idx];
    }
    for (int idx = t; idx < OUTD * Ss; idx += NT) {
        int o = idx >> 6, a = idx & 63;
        sm[OFF_WR + o * WRS + a] = Wr[idx];
    }
    for (int idx = t; idx < Hh; idx += NT) {
        sm[OFF_B0 + idx] = bv0[idx];
        sm[OFF_B1 + idx] = bv1[idx];
    }
    for (int idx = t; idx < 4 * Hh; idx += NT) sm[OFF_B2 + idx] = bv2[idx];
    if (t < 8) {
        sm[OFF_BR + t] = br[t];
        sm[OFF_X0 + t] = x[(size_t)b * Tt * Dd + t];
    }

    // ---- depth-2 log-signatures: one window per thread (t < 128) ----
    if (t < NWIN) {
        const float4* xr = reinterpret_cast<const float4*>(x + ((size_t)b * Tt + (size_t)t * WINW) * Dd);
        float prev[8], cum[8], s1a[8], lev[Pp];
        float4 p0 = xr[0], p1 = xr[1];
        prev[0] = p0.x; prev[1] = p0.y; prev[2] = p0.z; prev[3] = p0.w;
        prev[4] = p1.x; prev[5] = p1.y; prev[6] = p1.z; prev[7] = p1.w;
#pragma unroll
        for (int d = 0; d < 8; d++) { cum[d] = 0.0f; s1a[d] = 0.0f; }
#pragma unroll
        for (int p = 0; p < Pp; p++) lev[p] = 0.0f;
        for (int w = 0; w < WINW; w++) {
            float4 c0 = xr[2 * (w + 1)], c1 = xr[2 * (w + 1) + 1];
            float cur[8];
            cur[0] = c0.x; cur[1] = c0.y; cur[2] = c0.z; cur[3] = c0.w;
            cur[4] = c1.x; cur[5] = c1.y; cur[6] = c1.z; cur[7] = c1.w;
            float dl[8];
#pragma unroll
            for (int d = 0; d < 8; d++) dl[d] = cur[d] - prev[d];
            int p = 0;
#pragma unroll
            for (int i = 0; i < 7; i++)
#pragma unroll
                for (int j = i + 1; j < 8; j++) {
                    lev[p] = fmaf(cum[i], dl[j], fmaf(-cum[j], dl[i], lev[p]));
                    p++;
                }
#pragma unroll
            for (int d = 0; d < 8; d++) {
                s1a[d] += dl[d];
                cum[d] += dl[d];
                prev[d] = cur[d];
            }
        }
#pragma unroll
        for (int d = 0; d < 8; d++) sm[OFF_S1 + t * 8 + d] = s1a[d];
#pragma unroll
        for (int p = 0; p < Pp; p++) sm[OFF_S2 + t * Pp + p] = 0.5f * lev[p];
    }
    __syncthreads();

    // ---- initial MLP: h0 = Wi2 sp(Wi1 sp(Wi0 x0 + bi0) + bi1) + bi2 ----
    if (t < Hh) {
        float acc = bi0[t];
#pragma unroll
        for (int d = 0; d < 8; d++) acc = fmaf(__ldg(&Wi0[t * 8 + d]), sm[OFF_X0 + d], acc);
        sm[OFF_Z0 + t] = softplusf(acc);
    }
    __syncthreads();
    {
        int r = t >> 2, q = t & 3;
        float acc = 0.0f;
#pragma unroll 8
        for (int c = 0; c < 32; c++) {
            int k = q + 4 * c;
            acc = fmaf(__ldg(&Wi1[r * 128 + k]), sm[OFF_Z0 + k], acc);
        }
        acc += __shfl_xor_sync(0xffffffffu, acc, 1);
        acc += __shfl_xor_sync(0xffffffffu, acc, 2);
        if (q == 0) sm[OFF_Z1 + r] = softplusf(acc + bi1[r]);
    }
    __syncthreads();
    if (t < 4 * Ss) {
        int s_ = t >> 2, q = t & 3;
        float acc = 0.0f;
#pragma unroll 8
        for (int c = 0; c < 32; c++) {
            int k = q + 4 * c;
            acc = fmaf(__ldg(&Wi2[s_ * 128 + k]), sm[OFF_Z1 + k], acc);
        }
        acc += __shfl_xor_sync(0xffffffffu, acc, 1);
        acc += __shfl_xor_sync(0xffffffffu, acc, 2);
        if (q == 0) sm[OFF_HA + s_] = acc + bi2[s_];
    }
    __syncthreads();
    if (t < 8) {
        float acc = sm[OFF_BR + t];
#pragma unroll 8
        for (int a = 0; a < Ss; a++) acc = fmaf(sm[OFF_WR + t * WRS + a], sm[OFF_HA + a], acc);
        out[((size_t)b * (NWIN + 1)) * 8 + t] = acc;
    }
    __syncthreads();

    const float4* wt4 = reinterpret_cast<const float4*>(g_WT);

    // ---- scan over NWIN log-ODE steps (h double-buffered HA/HB) ----
    for (int n = 0; n < NWIN; n++) {
        const int hc = (n & 1) ? OFF_HB : OFF_HA;   // current h
        const int hx = (n & 1) ? OFF_HA : OFF_HB;   // next h
        // A: t0 = Wv0 h + bv0 -> z0, d0
        {
            int r = t >> 2, q = t & 3;
            float acc = 0.0f;
#pragma unroll
            for (int c = 0; c < 16; c++) {
                int k = q + 4 * c;
                acc = fmaf(sm[OFF_WV0 + r * W0S + k], sm[hc + k], acc);
            }
            acc += __shfl_xor_sync(0xffffffffu, acc, 1);
            acc += __shfl_xor_sync(0xffffffffu, acc, 2);
            if (q == 0) {
                float pre = acc + sm[OFF_B0 + r];
                sm[OFF_Z0 + r] = softplusf(pre);
                sm[OFF_D0 + r] = sigmf(pre);
            }
        }
        __syncthreads();
        // B: t1 = Wv1 z0 + bv1 -> z1, d1
        {
            int r = t >> 2, q = t & 3;
            float acc = 0.0f;
#pragma unroll 8
            for (int c = 0; c < 32; c++) {
                int k = q + 4 * c;
                acc = fmaf(sm[OFF_WV1 + r * W1S + k], sm[OFF_Z0 + k], acc);
            }
            acc += __shfl_xor_sync(0xffffffffu, acc, 1);
            acc += __shfl_xor_sync(0xffffffffu, acc, 2);
            if (q == 0) {
                float pre = acc + sm[OFF_B1 + r];
                sm[OFF_Z1 + r] = softplusf(pre);
                sm[OFF_D1 + r] = sigmf(pre);
            }
        }
        __syncthreads();
        // C: t2 = Wv2 z1 + bv2 ; V = tanh(t2)   (Wv2 streamed coalesced from L2)
        {
            float acc = sm[OFF_B2 + t];
            const float4* z14 = reinterpret_cast<const float4*>(&sm[OFF_Z1]);
#pragma unroll 8
            for (int c = 0; c < 32; c++) {
                float4 w = __ldg(&wt4[c * 512 + t]);
                float4 z = z14[c];
                acc = fmaf(w.x, z.x, acc);
                acc = fmaf(w.y, z.y, acc);
                acc = fmaf(w.z, z.z, acc);
                acc = fmaf(w.w, z.w, acc);
            }
            sm[OFF_V + (t >> 6) * VS + (t & 63)] = tanhf(acc);
        }
        __syncthreads();
        // D: u0[.,i] = d0 ⊙ (Wv0 @ V_i)   (8 tangent dirs, 2 per thread)
        {
            int r = t >> 2, sub = t & 3;
            float acc0 = 0.0f, acc1 = 0.0f;
#pragma unroll
            for (int c = 0; c < 16; c++) {
                float4 w  = *(const float4*)&sm[OFF_WV0 + r * W0S + 4 * c];
                float4 va = *(const float4*)&sm[OFF_V + sub * VS + 4 * c];
                float4 vb = *(const float4*)&sm[OFF_V + (sub + 4) * VS + 4 * c];
                acc0 = fmaf(w.x, va.x, acc0); acc0 = fmaf(w.y, va.y, acc0);
                acc0 = fmaf(w.z, va.z, acc0); acc0 = fmaf(w.w, va.w, acc0);
                acc1 = fmaf(w.x, vb.x, acc1); acc1 = fmaf(w.y, vb.y, acc1);
                acc1 = fmaf(w.z, vb.z, acc1); acc1 = fmaf(w.w, vb.w, acc1);
            }
            float dd = sm[OFF_D0 + r];
            sm[OFF_U0T + sub * U0S + r]       = dd * acc0;
            sm[OFF_U0T + (sub + 4) * U0S + r] = dd * acc1;
        }
        __syncthreads();
        // E: u1[.,i] = d1 ⊙ (Wv1 @ u0[.,i])
        {
            int r = t >> 2, sub = t & 3;
            float acc0 = 0.0f, acc1 = 0.0f;
#pragma unroll 8
            for (int c = 0; c < 32; c++) {
                float4 w  = *(const float4*)&sm[OFF_WV1 + r * W1S + 4 * c];
                float4 ua = *(const float4*)&sm[OFF_U0T + sub * U0S + 4 * c];
                float4 ub = *(const float4*)&sm[OFF_U0T + (sub + 4) * U0S + 4 * c];
                acc0 = fmaf(w.x, ua.x, acc0); acc0 = fmaf(w.y, ua.y, acc0);
                acc0 = fmaf(w.z, ua.z, acc0); acc0 = fmaf(w.w, ua.w, acc0);
                acc1 = fmaf(w.x, ub.x, acc1); acc1 = fmaf(w.y, ub.y, acc1);
                acc1 = fmaf(w.z, ub.z, acc1); acc1 = fmaf(w.w, ub.w, acc1);
            }
            float dd = sm[OFF_D1 + r];
            sm[OFF_U1 + r * 8 + sub]     = dd * acc0;
            sm[OFF_U1 + r * 8 + sub + 4] = dd * acc1;
        }
        __syncthreads();
        // F: W[.,i] = (1-V^2) ⊙ (Wv2 @ u1[.,i])  — packed f32x2 FMA, row per thread
        {
            unsigned long long a0 = 0ull, a1 = 0ull, a2 = 0ull, a3 = 0ull;
#pragma unroll 4
            for (int c = 0; c < 32; c++) {
                float4 w = __ldg(&wt4[c * 512 + t]);
                unsigned long long wp0 = pack2(w.x, w.x);
                unsigned long long wp1 = pack2(w.y, w.y);
                unsigned long long wp2 = pack2(w.z, w.z);
                unsigned long long wp3 = pack2(w.w, w.w);
#pragma unroll
                for (int j = 0; j < 4; j++) {
                    unsigned long long wp = (j == 0) ? wp0 : (j == 1) ? wp1 : (j == 2) ? wp2 : wp3;
                    int k = 4 * c + j;
                    ulonglong2 ua = *(const ulonglong2*)&sm[OFF_U1 + k * 8];
                    ulonglong2 ub = *(const ulonglong2*)&sm[OFF_U1 + k * 8 + 4];
                    a0 = fma2(wp, ua.x, a0);
                    a1 = fma2(wp, ua.y, a1);
                    a2 = fma2(wp, ub.x, a2);
                    a3 = fma2(wp, ub.y, a3);
                }
            }
            float v  = sm[OFF_V + (t >> 6) * VS + (t & 63)];
            float dt = 1.0f - v * v;
            float2 f0 = unpack2(a0), f1 = unpack2(a1), f2 = unpack2(a2), f3 = unpack2(a3);
            sm[OFF_WSMT + 0 * WTS + t] = dt * f0.x;
            sm[OFF_WSMT + 1 * WTS + t] = dt * f0.y;
            sm[OFF_WSMT + 2 * WTS + t] = dt * f1.x;
            sm[OFF_WSMT + 3 * WTS + t] = dt * f1.y;
            sm[OFF_WSMT + 4 * WTS + t] = dt * f2.x;
            sm[OFF_WSMT + 5 * WTS + t] = dt * f2.y;
            sm[OFF_WSMT + 6 * WTS + t] = dt * f3.x;
            sm[OFF_WSMT + 7 * WTS + t] = dt * f3.y;
        }
        __syncthreads();
        // update: hn = h + s1·V + s2·[V_i,V_j]  (writes the other h buffer)
        if (t < Ss) {
            float acc = sm[hc + t];
            const float* s1n = &sm[OFF_S1 + n * 8];
            const float* s2n = &sm[OFF_S2 + n * Pp];
#pragma unroll
            for (int i = 0; i < 8; i++) acc = fmaf(s1n[i], sm[OFF_V + i * VS + t], acc);
            int p = 0;
#pragma unroll
            for (int i = 0; i < 7; i++)
#pragma unroll
                for (int j = i + 1; j < 8; j++) {
                    float wji = sm[OFF_WSMT + i * WTS + j * 64 + t];  // JV[j,i,a]
                    float wij = sm[OFF_WSMT + j * WTS + i * 64 + t];  // JV[i,j,a]
                    acc = fmaf(s2n[p], wji - wij, acc);
                    p++;
                }
            sm[hx + t] = acc;
        }
        __syncthreads();
        // readout of new h (no extra barrier: next stage A only reads hx too)
        if (t >= Ss && t < Ss + 8) {
            int o = t - Ss;
            float acc = sm[OFF_BR + o];
#pragma unroll 8
            for (int a = 0; a < Ss; a++) acc = fmaf(sm[OFF_WR + o * WRS + a], sm[hx + a], acc);
            out[((size_t)b * (NWIN + 1) + (n + 1)) * 8 + o] = acc;
        }
    }
}

extern "C" void kernel_launch(void* const* d_in, const int* in_sizes, int n_in,
                              void* d_out, int out_size) {
    // metadata order: ts, x, Wi0, bi0, Wi1, bi1, Wi2, bi2, Wv0, bv0, Wv1, bv1, Wv2, bv2, Wr, br
    const float* x   = (const float*)d_in[1];
    const float* Wi0 = (const float*)d_in[2];
    const float* bi0 = (const float*)d_in[3];
    const float* Wi1 = (const float*)d_in[4];
    const float* bi1 = (const float*)d_in[5];
    const float* Wi2 = (const float*)d_in[6];
    const float* bi2 = (const float*)d_in[7];
    const float* Wv0 = (const float*)d_in[8];
    const float* bv0 = (const float*)d_in[9];
    const float* Wv1 = (const float*)d_in[10];
    const float* bv1 = (const float*)d_in[11];
    const float* Wv2 = (const float*)d_in[12];
    const float* bv2 = (const float*)d_in[13];
    const float* Wr  = (const float*)d_in[14];
    const float* br  = (const float*)d_in[15];

    size_t smem = (size_t)SMEM_FLOATS * sizeof(float);
    cudaFuncSetAttribute(logncde_kernel, cudaFuncAttributeMaxDynamicSharedMemorySize, (int)smem);

    wt_transpose_kernel<<<(512 * 128 + 255) / 256, 256>>>(Wv2);
    logncde_kernel<<<Bb, NT, smem>>>(x, Wi0, bi0, Wi1, bi1, Wi2, bi2,
                                     Wv0, bv0, Wv1, bv1, bv2, Wr, br,
                                     (float*)d_out);
}

// round 7
// speedup vs baseline: 1.3641x; 1.3641x over previous
#include <cuda_runtime.h>
#include <math.h>

// ---------------- problem constants ----------------
#define Dd   8
#define Ss   64
#define Hh   128
#define OUTD 8
#define Tt   2049
#define Bb   32
#define WINW 16
#define NWIN 128
#define Pp   28
#define NT   512

// padded smem strides
#define W0S 68
#define W1S 132
#define VS  68
#define U0S 132
#define U1S 136
#define WRS 68

// smem float offsets (all multiples of 4)
#define OFF_WV0  0
#define OFF_WV1  (OFF_WV0 + 128*W0S)      // 8704
#define OFF_U0T  (OFF_WV1 + 128*W1S)      // 25600
#define OFF_U1T  (OFF_U0T + 8*U0S)        // 26656
#define OFF_V    (OFF_U1T + 8*U1S)        // 27744
#define OFF_WROT (OFF_V   + 8*VS)         // 28288
#define OFF_BB   (OFF_WROT+ 8*VS)         // 28832
#define OFF_WR   (OFF_BB  + 512)          // 29344
#define OFF_S1   (OFF_WR  + 8*WRS)        // 29888
#define OFF_S2   (OFF_S1  + NWIN*Dd)      // 30912
#define OFF_Z0   (OFF_S2  + NWIN*Pp)      // 34496
#define OFF_D0   (OFF_Z0  + 128)
#define OFF_Z1   (OFF_D0  + 128)
#define OFF_D1   (OFF_Z1  + 128)
#define OFF_HA   (OFF_D1  + 128)
#define OFF_HB   (OFF_HA  + 64)
#define OFF_B0   (OFF_HB  + 64)
#define OFF_B1   (OFF_B0  + 128)
#define OFF_B2   (OFF_B1  + 128)
#define OFF_BR   (OFF_B2  + 512)
#define OFF_X0   (OFF_BR  + 8)
#define SMEM_FLOATS (OFF_X0 + 8)

// Wv2 (512x128) pre-transposed: wt4[c*512 + r] = float4 Wv2[r, 4c..4c+3]
__device__ float g_WT[512 * 128];

__global__ void wt_transpose_kernel(const float* __restrict__ Wv2) {
    int idx = blockIdx.x * blockDim.x + threadIdx.x;
    if (idx < 512 * 128) {
        int r = idx >> 7, k = idx & 127;
        int c = k >> 2, j = k & 3;
        g_WT[(c * 512 + r) * 4 + j] = Wv2[idx];
    }
}

__device__ __forceinline__ float softplusf(float x) {
    return fmaxf(x, 0.0f) + log1pf(expf(-fabsf(x)));
}
__device__ __forceinline__ float sigmf(float x) {
    return 1.0f / (1.0f + expf(-x));
}

__global__ __launch_bounds__(NT, 1)
void logncde_kernel(const float* __restrict__ x,
                    const float* __restrict__ Wi0, const float* __restrict__ bi0,
                    const float* __restrict__ Wi1, const float* __restrict__ bi1,
                    const float* __restrict__ Wi2, const float* __restrict__ bi2,
                    const float* __restrict__ Wv0, const float* __restrict__ bv0,
                    const float* __restrict__ Wv1, const float* __restrict__ bv1,
                    const float* __restrict__ bv2,
                    const float* __restrict__ Wr,  const float* __restrict__ br,
                    float* __restrict__ out)
{
    extern __shared__ float sm[];
    const int t = threadIdx.x;
    const int b = blockIdx.x;

    // ---- load weights into padded smem ----
    for (int idx = t; idx < Hh * Ss; idx += NT) {
        int r = idx >> 6, a = idx & 63;
        sm[OFF_WV0 + r * W0S + a] = Wv0[idx];
    }
    for (int idx = t; idx < Hh * Hh; idx += NT) {
        int r = idx >> 7, k = idx & 127;
        sm[OFF_WV1 + r * W1S + k] = Wv1[idx];
    }
    for (int idx = t; idx < OUTD * Ss; idx += NT) {
        int o = idx >> 6, a = idx & 63;
        sm[OFF_WR + o * WRS + a] = Wr[idx];
    }
    for (int idx = t; idx < Hh; idx += NT) {
        sm[OFF_B0 + idx] = bv0[idx];
        sm[OFF_B1 + idx] = bv1[idx];
    }
    for (int idx = t; idx < 4 * Hh; idx += NT) sm[OFF_B2 + idx] = bv2[idx];
    if (t < 8) {
        sm[OFF_BR + t] = br[t];
        sm[OFF_X0 + t] = x[(size_t)b * Tt * Dd + t];
    }

    // ---- depth-2 log-signatures: one window per thread (t < 128) ----
    if (t < NWIN) {
        const float4* xr = reinterpret_cast<const float4*>(x + ((size_t)b * Tt + (size_t)t * WINW) * Dd);
        float prev[8], cum[8], s1a[8], lev[Pp];
        float4 p0 = xr[0], p1 = xr[1];
        prev[0] = p0.x; prev[1] = p0.y; prev[2] = p0.z; prev[3] = p0.w;
        prev[4] = p1.x; prev[5] = p1.y; prev[6] = p1.z; prev[7] = p1.w;
#pragma unroll
        for (int d = 0; d < 8; d++) { cum[d] = 0.0f; s1a[d] = 0.0f; }
#pragma unroll
        for (int p = 0; p < Pp; p++) lev[p] = 0.0f;
        for (int w = 0; w < WINW; w++) {
            float4 c0 = xr[2 * (w + 1)], c1 = xr[2 * (w + 1) + 1];
            float cur[8];
            cur[0] = c0.x; cur[1] = c0.y; cur[2] = c0.z; cur[3] = c0.w;
            cur[4] = c1.x; cur[5] = c1.y; cur[6] = c1.z; cur[7] = c1.w;
            float dl[8];
#pragma unroll
            for (int d = 0; d < 8; d++) dl[d] = cur[d] - prev[d];
            int p = 0;
#pragma unroll
            for (int i = 0; i < 7; i++)
#pragma unroll
                for (int j = i + 1; j < 8; j++) {
                    lev[p] = fmaf(cum[i], dl[j], fmaf(-cum[j], dl[i], lev[p]));
                    p++;
                }
#pragma unroll
            for (int d = 0; d < 8; d++) {
                s1a[d] += dl[d];
                cum[d] += dl[d];
                prev[d] = cur[d];
            }
        }
#pragma unroll
        for (int d = 0; d < 8; d++) sm[OFF_S1 + t * 8 + d] = s1a[d];
#pragma unroll
        for (int p = 0; p < Pp; p++) sm[OFF_S2 + t * Pp + p] = 0.5f * lev[p];
    }
    __syncthreads();

    // ---- initial MLP: h0 = Wi2 sp(Wi1 sp(Wi0 x0 + bi0) + bi1) + bi2 ----
    if (t < Hh) {
        float acc = bi0[t];
#pragma unroll
        for (int d = 0; d < 8; d++) acc = fmaf(__ldg(&Wi0[t * 8 + d]), sm[OFF_X0 + d], acc);
        sm[OFF_Z0 + t] = softplusf(acc);
    }
    __syncthreads();
    {
        int r = t >> 2, q = t & 3;
        float acc = 0.0f;
#pragma unroll 8
        for (int c = 0; c < 32; c++) {
            int k = q + 4 * c;
            acc = fmaf(__ldg(&Wi1[r * 128 + k]), sm[OFF_Z0 + k], acc);
        }
        acc += __shfl_xor_sync(0xffffffffu, acc, 1);
        acc += __shfl_xor_sync(0xffffffffu, acc, 2);
        if (q == 0) sm[OFF_Z1 + r] = softplusf(acc + bi1[r]);
    }
    __syncthreads();
    if (t < 4 * Ss) {
        int s_ = t >> 2, q = t & 3;
        float acc = 0.0f;
#pragma unroll 8
        for (int c = 0; c < 32; c++) {
            int k = q + 4 * c;
            acc = fmaf(__ldg(&Wi2[s_ * 128 + k]), sm[OFF_Z1 + k], acc);
        }
        acc += __shfl_xor_sync(0xffffffffu, acc, 1);
        acc += __shfl_xor_sync(0xffffffffu, acc, 2);
        if (q == 0) sm[OFF_HA + s_] = acc + bi2[s_];
    }
    __syncthreads();
    if (t < 8) {
        float acc = sm[OFF_BR + t];
#pragma unroll 8
        for (int a = 0; a < Ss; a++) acc = fmaf(sm[OFF_WR + t * WRS + a], sm[OFF_HA + a], acc);
        out[((size_t)b * (NWIN + 1)) * 8 + t] = acc;
    }
    __syncthreads();

    const float4* wt4 = reinterpret_cast<const float4*>(g_WT);

    // ---- scan over NWIN log-ODE steps (h double-buffered HA/HB) ----
    for (int n = 0; n < NWIN; n++) {
        const int hc = (n & 1) ? OFF_HB : OFF_HA;   // current h
        const int hx = (n & 1) ? OFF_HA : OFF_HB;   // next h
        // A: t0 = Wv0 h + bv0 -> z0, d0
        {
            int r = t >> 2, q = t & 3;
            float acc = 0.0f;
#pragma unroll
            for (int c = 0; c < 16; c++) {
                int k = q + 4 * c;
                acc = fmaf(sm[OFF_WV0 + r * W0S + k], sm[hc + k], acc);
            }
            acc += __shfl_xor_sync(0xffffffffu, acc, 1);
            acc += __shfl_xor_sync(0xffffffffu, acc, 2);
            if (q == 0) {
                float pre = acc + sm[OFF_B0 + r];
                sm[OFF_Z0 + r] = softplusf(pre);
                sm[OFF_D0 + r] = sigmf(pre);
            }
        }
        __syncthreads();
        // B: t1 = Wv1 z0 + bv1 -> z1, d1
        {
            int r = t >> 2, q = t & 3;
            float acc = 0.0f;
#pragma unroll 8
            for (int c = 0; c < 32; c++) {
                int k = q + 4 * c;
                acc = fmaf(sm[OFF_WV1 + r * W1S + k], sm[OFF_Z0 + k], acc);
            }
            acc += __shfl_xor_sync(0xffffffffu, acc, 1);
            acc += __shfl_xor_sync(0xffffffffu, acc, 2);
            if (q == 0) {
                float pre = acc + sm[OFF_B1 + r];
                sm[OFF_Z1 + r] = softplusf(pre);
                sm[OFF_D1 + r] = sigmf(pre);
            }
        }
        __syncthreads();
        // C: t2 = Wv2 z1 + bv2 ; V = tanh(t2)   (Wv2 streamed coalesced from L2)
        {
            float acc = sm[OFF_B2 + t];
            const float4* z14 = reinterpret_cast<const float4*>(&sm[OFF_Z1]);
#pragma unroll 8
            for (int c = 0; c < 32; c++) {
                float4 w = __ldg(&wt4[c * 512 + t]);
                float4 z = z14[c];
                acc = fmaf(w.x, z.x, acc);
                acc = fmaf(w.y, z.y, acc);
                acc = fmaf(w.z, z.z, acc);
                acc = fmaf(w.w, z.w, acc);
            }
            sm[OFF_V + (t >> 6) * VS + (t & 63)] = tanhf(acc);
        }
        __syncthreads();
        // W: rotate V by the antisymmetric s2-matrix: w_d = sum_e c[d,e] V_e
        //    c[d,e] = +s2[p(e,d)] for e<d, -s2[p(d,e)] for e>d  (p = triu pair index)
        {
            int d = t >> 6, a = t & 63;
            const float* s2n = &sm[OFF_S2 + n * Pp];
            float acc = 0.0f;
#pragma unroll
            for (int e = 0; e < 8; e++) {
                if (e == d) continue;
                int i = e < d ? e : d;
                int j = e < d ? d : e;
                int p = i * 7 - ((i * (i - 1)) >> 1) + (j - i - 1);
                float coef = (e < d) ? s2n[p] : -s2n[p];
                acc = fmaf(coef, sm[OFF_V + e * VS + a], acc);
            }
            sm[OFF_WROT + d * VS + a] = acc;
        }
        __syncthreads();
        // D: u0[.,d] = d0 ⊙ (Wv0 @ w_d)   (8 rotated dirs, 2 per thread)
        {
            int r = t >> 2, sub = t & 3;
            float acc0 = 0.0f, acc1 = 0.0f;
#pragma unroll
            for (int c = 0; c < 16; c++) {
                float4 w  = *(const float4*)&sm[OFF_WV0 + r * W0S + 4 * c];
                float4 va = *(const float4*)&sm[OFF_WROT + sub * VS + 4 * c];
                float4 vb = *(const float4*)&sm[OFF_WROT + (sub + 4) * VS + 4 * c];
                acc0 = fmaf(w.x, va.x, acc0); acc0 = fmaf(w.y, va.y, acc0);
                acc0 = fmaf(w.z, va.z, acc0); acc0 = fmaf(w.w, va.w, acc0);
                acc1 = fmaf(w.x, vb.x, acc1); acc1 = fmaf(w.y, vb.y, acc1);
                acc1 = fmaf(w.z, vb.z, acc1); acc1 = fmaf(w.w, vb.w, acc1);
            }
            float dd = sm[OFF_D0 + r];
            sm[OFF_U0T + sub * U0S + r]       = dd * acc0;
            sm[OFF_U0T + (sub + 4) * U0S + r] = dd * acc1;
        }
        __syncthreads();
        // E: u1[.,d] = d1 ⊙ (Wv1 @ u0[.,d])
        {
            int r = t >> 2, sub = t & 3;
            float acc0 = 0.0f, acc1 = 0.0f;
#pragma unroll 8
            for (int c = 0; c < 32; c++) {
                float4 w  = *(const float4*)&sm[OFF_WV1 + r * W1S + 4 * c];
                float4 ua = *(const float4*)&sm[OFF_U0T + sub * U0S + 4 * c];
                float4 ub = *(const float4*)&sm[OFF_U0T + (sub + 4) * U0S + 4 * c];
                acc0 = fmaf(w.x, ua.x, acc0); acc0 = fmaf(w.y, ua.y, acc0);
                acc0 = fmaf(w.z, ua.z, acc0); acc0 = fmaf(w.w, ua.w, acc0);
                acc1 = fmaf(w.x, ub.x, acc1); acc1 = fmaf(w.y, ub.y, acc1);
                acc1 = fmaf(w.z, ub.z, acc1); acc1 = fmaf(w.w, ub.w, acc1);
            }
            float dd = sm[OFF_D1 + r];
            sm[OFF_U1T + sub * U1S + r]       = dd * acc0;
            sm[OFF_U1T + (sub + 4) * U1S + r] = dd * acc1;
        }
        __syncthreads();
        // F: bb_partial[d,a] = (1-V[d,a]^2) * (Wv2[d*64+a,:] @ u1_d)
        //    thread t handles row t = d*64+a; u1_d broadcast across the warp
        {
            int d = t >> 6;
            float acc = 0.0f;
            const float4* u14 = reinterpret_cast<const float4*>(&sm[OFF_U1T + d * U1S]);
#pragma unroll 8
            for (int c = 0; c < 32; c++) {
                float4 w = __ldg(&wt4[c * 512 + t]);
                float4 u = u14[c];
                acc = fmaf(w.x, u.x, acc);
                acc = fmaf(w.y, u.y, acc);
                acc = fmaf(w.z, u.z, acc);
                acc = fmaf(w.w, u.w, acc);
            }
            float v  = sm[OFF_V + d * VS + (t & 63)];
            float dt = 1.0f - v * v;
            sm[OFF_BB + t] = dt * acc;
        }
        __syncthreads();
        // update: hn = h + s1·V + sum_d bb_partial[d]
        if (t < Ss) {
            float acc = sm[hc + t];
            const float* s1n = &sm[OFF_S1 + n * 8];
#pragma unroll
            for (int i = 0; i < 8; i++) acc = fmaf(s1n[i], sm[OFF_V + i * VS + t], acc);
#pragma unroll
            for (int d = 0; d < 8; d++) acc += sm[OFF_BB + d * 64 + t];
            sm[hx + t] = acc;
        }
        __syncthreads();
        // readout of new h (no extra barrier: next stage A only reads hx too)
        if (t >= Ss && t < Ss + 8) {
            int o = t - Ss;
            float acc = sm[OFF_BR + o];
#pragma unroll 8
            for (int a = 0; a < Ss; a++) acc = fmaf(sm[OFF_WR + o * WRS + a], sm[hx + a], acc);
            out[((size_t)b * (NWIN + 1) + (n + 1)) * 8 + o] = acc;
        }
    }
}

extern "C" void kernel_launch(void* const* d_in, const int* in_sizes, int n_in,
                              void* d_out, int out_size) {
    // metadata order: ts, x, Wi0, bi0, Wi1, bi1, Wi2, bi2, Wv0, bv0, Wv1, bv1, Wv2, bv2, Wr, br
    const float* x   = (const float*)d_in[1];
    const float* Wi0 = (const float*)d_in[2];
    const float* bi0 = (const float*)d_in[3];
    const float* Wi1 = (const float*)d_in[4];
    const float* bi1 = (const float*)d_in[5];
    const float* Wi2 = (const float*)d_in[6];
    const float* bi2 = (const float*)d_in[7];
    const float* Wv0 = (const float*)d_in[8];
    const float* bv0 = (const float*)d_in[9];
    const float* Wv1 = (const float*)d_in[10];
    const float* bv1 = (const float*)d_in[11];
    const float* Wv2 = (const float*)d_in[12];
    const float* bv2 = (const float*)d_in[13];
    const float* Wr  = (const float*)d_in[14];
    const float* br  = (const float*)d_in[15];

    size_t smem = (size_t)SMEM_FLOATS * sizeof(float);
    cudaFuncSetAttribute(logncde_kernel, cudaFuncAttributeMaxDynamicSharedMemorySize, (int)smem);

    wt_transpose_kernel<<<(512 * 128 + 255) / 256, 256>>>(Wv2);
    logncde_kernel<<<Bb, NT, smem>>>(x, Wi0, bi0, Wi1, bi1, Wi2, bi2,
                                     Wv0, bv0, Wv1, bv1, bv2, Wr, br,
                                     (float*)d_out);
}